// round 7
// baseline (speedup 1.0000x reference)
#include <cuda_runtime.h>

#define BB 2
#define CC 128
#define HH 128
#define WW 256
#define KK 20
#define HW (HH * WW)
#define EPSV 1e-12f

typedef unsigned long long u64;

__device__ __forceinline__ u64 pk2(float lo, float hi) {
    u64 r; asm("mov.b64 %0, {%1,%2};" : "=l"(r) : "f"(lo), "f"(hi)); return r;
}
__device__ __forceinline__ void upk2(u64 v, float& lo, float& hi) {
    asm("mov.b64 {%0,%1}, %2;" : "=f"(lo), "=f"(hi) : "l"(v));
}
__device__ __forceinline__ u64 fma2_(u64 a, u64 b, u64 c) {
    u64 d; asm("fma.rn.f32x2 %0, %1, %2, %3;" : "=l"(d) : "l"(a), "l"(b), "l"(c)); return d;
}
__device__ __forceinline__ u64 mul2_(u64 a, u64 b) {
    u64 d; asm("mul.rn.f32x2 %0, %1, %2;" : "=l"(d) : "l"(a), "l"(b)); return d;
}
__device__ __forceinline__ u64 add2_(u64 a, u64 b) {
    u64 d; asm("add.rn.f32x2 %0, %1, %2;" : "=l"(d) : "l"(a), "l"(b)); return d;
}
__device__ __forceinline__ float wred(float v) {
#pragma unroll
    for (int o = 16; o > 0; o >>= 1) v += __shfl_xor_sync(0xffffffffu, v, o);
    return v;
}
__device__ __forceinline__ float dot4(float4 a) {
    return a.x * a.x + a.y * a.y + a.z * a.z + a.w * a.w;
}

// 16-c segment. Thread owns 4 px (2 packed pairs) x 10 k.
// Prototype row: s_pn[c][k] (20 u64, k contiguous); this thread reads kh*10..+10
// as 5 LDS.128. DO_S2 threads also accumulate ||fn||^2 over this segment.
template <bool DO_S2>
__device__ __forceinline__ void seg16(const float4* __restrict__ fp, int ccb,
                                      const u64* __restrict__ pb,    // s_pn + c0*20 + kh*10
                                      const u64* __restrict__ r2b,   // s_r2 + c0
                                      u64 acc[10][2], u64 s2[2]) {
#pragma unroll 4
    for (int t = 0; t < 16; t++) {
        int cc = ccb + t;
        float4 xv = fp[(size_t)cc * (HW / 4)];
        u64 x0 = pk2(xv.x, xv.y);
        u64 x1 = pk2(xv.z, xv.w);
        const u64* pr = pb + cc * 20;
        ulonglong2 q0 = *(const ulonglong2*)(pr);
        ulonglong2 q1 = *(const ulonglong2*)(pr + 2);
        ulonglong2 q2 = *(const ulonglong2*)(pr + 4);
        ulonglong2 q3 = *(const ulonglong2*)(pr + 6);
        ulonglong2 q4 = *(const ulonglong2*)(pr + 8);
        acc[0][0] = fma2_(x0, q0.x, acc[0][0]); acc[0][1] = fma2_(x1, q0.x, acc[0][1]);
        acc[1][0] = fma2_(x0, q0.y, acc[1][0]); acc[1][1] = fma2_(x1, q0.y, acc[1][1]);
        acc[2][0] = fma2_(x0, q1.x, acc[2][0]); acc[2][1] = fma2_(x1, q1.x, acc[2][1]);
        acc[3][0] = fma2_(x0, q1.y, acc[3][0]); acc[3][1] = fma2_(x1, q1.y, acc[3][1]);
        acc[4][0] = fma2_(x0, q2.x, acc[4][0]); acc[4][1] = fma2_(x1, q2.x, acc[4][1]);
        acc[5][0] = fma2_(x0, q2.y, acc[5][0]); acc[5][1] = fma2_(x1, q2.y, acc[5][1]);
        acc[6][0] = fma2_(x0, q3.x, acc[6][0]); acc[6][1] = fma2_(x1, q3.x, acc[6][1]);
        acc[7][0] = fma2_(x0, q3.y, acc[7][0]); acc[7][1] = fma2_(x1, q3.y, acc[7][1]);
        acc[8][0] = fma2_(x0, q4.x, acc[8][0]); acc[8][1] = fma2_(x1, q4.x, acc[8][1]);
        acc[9][0] = fma2_(x0, q4.y, acc[9][0]); acc[9][1] = fma2_(x1, q4.y, acc[9][1]);
        if (DO_S2) {
            u64 r2 = r2b[cc];
            s2[0] = fma2_(mul2_(x0, r2), x0, s2[0]);
            s2[1] = fma2_(mul2_(x1, r2), x1, s2[1]);
        }
    }
}

// Fused kernel. Block = (b,h), 512 threads.
// tid: pxg bits0-5 (64 groups x 4 px), kh bit6 (2 k-halves of 10), cg bits7-8 (4 c-groups of 32).
__global__ __launch_bounds__(512, 2) void iso_kernel(const float* __restrict__ f,
                                                     const float* __restrict__ p,
                                                     const float* __restrict__ ds,
                                                     float* __restrict__ out) {
    __shared__ u64 s_pn[CC * 20];    // [c][k] folded protos (20 KB); aliased as s_red after
    __shared__ u64 s_s2p[8 * 128];   // s2 partials per (cg*2+kh) group (8 KB)
    __shared__ u64 s_s2[128];        // final per pixel-pair (1 KB)
    __shared__ u64 s_r2[CC];
    __shared__ float s_inv[CC];
    __shared__ float s_pinv[KK];
    __shared__ float s_pn2[KK];

    int tid = threadIdx.x;
    int w = tid >> 5, lane = tid & 31;
    int b = blockIdx.x / HH, h = blockIdx.x % HH;
    const float* fbh = f + (size_t)b * CC * HW + (size_t)h * WW;

    // ---- Pass 1a: W-norms; warp w handles c = w + 16j (8 c/warp, 4-row batches)
#pragma unroll
    for (int jb = 0; jb < 2; jb++) {
        float4 v[8];
        int cbase = w + jb * 64;
#pragma unroll
        for (int j = 0; j < 4; j++) {
            const float4* r4 = (const float4*)(fbh + (size_t)(cbase + 16 * j) * HW);
            v[2 * j]     = r4[lane];
            v[2 * j + 1] = r4[lane + 32];
        }
#pragma unroll
        for (int j = 0; j < 4; j++) {
            float s = wred(dot4(v[2 * j]) + dot4(v[2 * j + 1]));
            if (lane == 0) {
                int c = cbase + 16 * j;
                float r = 1.0f / fmaxf(sqrtf(s), EPSV);
                s_inv[c] = r;
                s_r2[c] = pk2(r * r, r * r);
            }
        }
    }
    // ---- Pass 1b: prototype norms
    for (int k = w; k < KK; k += 16) {
        float4 a = ((const float4*)(p + k * CC))[lane];
        float s = wred(dot4(a));
        if (lane == 0) {
            float inv = 1.0f / fmaxf(sqrtf(s), EPSV);
            s_pinv[k] = inv;
            s_pn2[k] = s * inv * inv;
        }
    }
    __syncthreads();

    // ---- Folded prototype table: s_pn[c*20 + k] = p[k][c] * pinv_k * inv_c (dup-packed)
    for (int i = tid; i < CC * KK; i += 512) {
        int c = i / KK, k = i - c * KK;
        float val = __ldg(p + k * CC + c) * s_pinv[k] * s_inv[c];
        s_pn[c * 20 + k] = pk2(val, val);
    }
    __syncthreads();

    // ---- Main dot loop
    int pxg = tid & 63;
    int kh = (tid >> 6) & 1;
    int cg = tid >> 7;
    int c0 = cg * 32;

    const float4* fp = (const float4*)fbh + (size_t)c0 * (HW / 4) + pxg;
    const u64* pb = s_pn + (size_t)c0 * 20 + kh * 10;
    const u64* r2b = s_r2 + c0;

    u64 acc[10][2];
#pragma unroll
    for (int j = 0; j < 10; j++) { acc[j][0] = 0ull; acc[j][1] = 0ull; }
    u64 s2[2] = {0ull, 0ull};

    if (kh == 0) { seg16<true >(fp, 0, pb, r2b, acc, s2); seg16<false>(fp, 16, pb, r2b, acc, s2); }
    else         { seg16<false>(fp, 0, pb, r2b, acc, s2); seg16<true >(fp, 16, pb, r2b, acc, s2); }

    // ---- s2 reduction over 8 (cg,kh) groups
    int grp = cg * 2 + kh;
    s_s2p[(size_t)grp * 128 + 2 * pxg]     = s2[0];
    s_s2p[(size_t)grp * 128 + 2 * pxg + 1] = s2[1];
    __syncthreads();
    if (tid < 128) {
        u64 t = 0ull;
#pragma unroll
        for (int g = 0; g < 8; g++) t = add2_(t, s_s2p[g * 128 + tid]);
        s_s2[tid] = t;
    }

    // ---- k-chunked cross-cg reduction + epilogue (aliases s_pn; fully unrolled so
    //      acc indices stay compile-time constants)
    u64* s_red = s_pn;
    int slot = tid & 127;           // pxg + 64*kh
    float scale = fabsf(ds[0]);
#pragma unroll
    for (int chunk = 0; chunk < 5; chunk++) {
        __syncthreads();
        u64* wr = s_red + (size_t)tid * 4;   // ((cg*128+slot)*2+j)*2+i, j in {0,1}
        wr[0] = acc[2 * chunk][0];
        wr[1] = acc[2 * chunk][1];
        wr[2] = acc[2 * chunk + 1][0];
        wr[3] = acc[2 * chunk + 1][1];
        __syncthreads();
        if (tid < 256) {
            int sl = tid & 127, j = tid >> 7;
            int pxg2 = sl & 63, kh2 = sl >> 6;
            u64 a0 = 0ull, a1 = 0ull;
#pragma unroll
            for (int g = 0; g < 4; g++) {
                ulonglong2 q = *(const ulonglong2*)(s_red + ((size_t)(g * 128 + sl) * 2 + j) * 2);
                a0 = add2_(a0, q.x);
                a1 = add2_(a1, q.y);
            }
            int k = kh2 * 10 + chunk * 2 + j;
            float n0, n1, n2, n3;
            upk2(s_s2[2 * pxg2], n0, n1);
            upk2(s_s2[2 * pxg2 + 1], n2, n3);
            float qq = s_pn2[k];
            float d0, d1, d2, d3;
            upk2(a0, d0, d1);
            upk2(a1, d2, d3);
            float4 o;
            o.x = -scale * sqrtf(fmaxf(n0 + qq - 2.0f * d0, 0.0f));
            o.y = -scale * sqrtf(fmaxf(n1 + qq - 2.0f * d1, 0.0f));
            o.z = -scale * sqrtf(fmaxf(n2 + qq - 2.0f * d2, 0.0f));
            o.w = -scale * sqrtf(fmaxf(n3 + qq - 2.0f * d3, 0.0f));
            *(float4*)(out + ((size_t)b * KK + k) * HW + (size_t)h * WW + 4 * pxg2) = o;
        }
    }
}

extern "C" void kernel_launch(void* const* d_in, const int* in_sizes, int n_in,
                              void* d_out, int out_size) {
    const float* features   = (const float*)d_in[0];
    const float* prototypes = (const float*)d_in[1];
    const float* dscale     = (const float*)d_in[2];
    float* out = (float*)d_out;

    iso_kernel<<<BB * HH, 512>>>(features, prototypes, dscale, out);
}

// round 8
// speedup vs baseline: 1.0849x; 1.0849x over previous
#include <cuda_runtime.h>

#define BB 2
#define CC 128
#define HH 128
#define WW 256
#define KK 20
#define HW (HH * WW)
#define EPSV 1e-12f

typedef unsigned long long u64;

__device__ __forceinline__ u64 pk2(float lo, float hi) {
    u64 r; asm("mov.b64 %0, {%1,%2};" : "=l"(r) : "f"(lo), "f"(hi)); return r;
}
__device__ __forceinline__ void upk2(u64 v, float& lo, float& hi) {
    asm("mov.b64 {%0,%1}, %2;" : "=f"(lo), "=f"(hi) : "l"(v));
}
__device__ __forceinline__ u64 fma2_(u64 a, u64 b, u64 c) {
    u64 d; asm("fma.rn.f32x2 %0, %1, %2, %3;" : "=l"(d) : "l"(a), "l"(b), "l"(c)); return d;
}
__device__ __forceinline__ u64 mul2_(u64 a, u64 b) {
    u64 d; asm("mul.rn.f32x2 %0, %1, %2;" : "=l"(d) : "l"(a), "l"(b)); return d;
}
__device__ __forceinline__ u64 add2_(u64 a, u64 b) {
    u64 d; asm("add.rn.f32x2 %0, %1, %2;" : "=l"(d) : "l"(a), "l"(b)); return d;
}
__device__ __forceinline__ float wred(float v) {
#pragma unroll
    for (int o = 16; o > 0; o >>= 1) v += __shfl_xor_sync(0xffffffffu, v, o);
    return v;
}
__device__ __forceinline__ float dot4(float4 a) {
    return a.x * a.x + a.y * a.y + a.z * a.z + a.w * a.w;
}

// 8-c segment, x from SMEM. Padded proto rows: (cl*4+kg)*6 -> 2x LDS.128 + LDS.64.
template <bool DO_S2>
__device__ __forceinline__ void seg8(const float* __restrict__ sx, int clb, int pxg,
                                     const u64* __restrict__ pb,   // s_pn + kg*6
                                     const u64* __restrict__ r2b,  // s_r2 (cl-local)
                                     u64 acc[2][5], u64 s2[2]) {
#pragma unroll
    for (int t = 0; t < 8; t++) {
        int cl = clb + t;
        float4 xv = *(const float4*)(sx + cl * 256 + pxg * 4);
        u64 x0 = pk2(xv.x, xv.y);
        u64 x1 = pk2(xv.z, xv.w);
        const u64* pr = pb + cl * 24;
        ulonglong2 q0 = *(const ulonglong2*)(pr);
        ulonglong2 q1 = *(const ulonglong2*)(pr + 2);
        u64 p4 = pr[4];
        acc[0][0] = fma2_(x0, q0.x, acc[0][0]);
        acc[1][0] = fma2_(x1, q0.x, acc[1][0]);
        acc[0][1] = fma2_(x0, q0.y, acc[0][1]);
        acc[1][1] = fma2_(x1, q0.y, acc[1][1]);
        acc[0][2] = fma2_(x0, q1.x, acc[0][2]);
        acc[1][2] = fma2_(x1, q1.x, acc[1][2]);
        acc[0][3] = fma2_(x0, q1.y, acc[0][3]);
        acc[1][3] = fma2_(x1, q1.y, acc[1][3]);
        acc[0][4] = fma2_(x0, p4, acc[0][4]);
        acc[1][4] = fma2_(x1, p4, acc[1][4]);
        if (DO_S2) {
            u64 r2 = r2b[cl];
            s2[0] = fma2_(mul2_(x0, r2), x0, s2[0]);
            s2[1] = fma2_(mul2_(x1, r2), x1, s2[1]);
        }
    }
}

// Fused kernel, SMEM-staged. Block = (b,h), 512 threads, 2 c-phases of 64.
// tid: pxg bits0-5 (64 x 4 px), kg bits6-7 (4 x 5 k), ch bit8 (c-half of phase).
__global__ __launch_bounds__(512, 2) void iso_kernel(const float* __restrict__ f,
                                                     const float* __restrict__ p,
                                                     const float* __restrict__ ds,
                                                     float* __restrict__ out) {
    extern __shared__ float s_x[];      // [64 c][256 px] = 64 KB (dynamic)
    __shared__ u64 s_pn[64 * 24];       // padded folded protos for current phase (12 KB)
    __shared__ u64 s_s2p[8 * 128];      // s2 partials per (ch*4+kg) group (8 KB)
    __shared__ u64 s_s2[128];           // final ||fn||^2 per pixel pair (1 KB)
    __shared__ u64 s_r2[64];            // inv_c^2 (phase-local), dup-packed
    __shared__ float s_inv[64];
    __shared__ float s_pinv[KK];
    __shared__ float s_pn2[KK];

    int tid = threadIdx.x;
    int w = tid >> 5, lane = tid & 31;
    int b = blockIdx.x / HH, h = blockIdx.x % HH;
    const float* fbh = f + (size_t)b * CC * HW + (size_t)h * WW;

    // ---- Prototype norms (once; from GMEM, tiny)
    for (int k = w; k < KK; k += 16) {
        float4 a = ((const float4*)(p + k * CC))[lane];
        float s = wred(dot4(a));
        if (lane == 0) {
            float inv = 1.0f / fmaxf(sqrtf(s), EPSV);
            s_pinv[k] = inv;
            s_pn2[k] = s * inv * inv;
        }
    }

    int pxg = tid & 63;
    int kg = (tid >> 6) & 3;
    int ch = tid >> 8;

    u64 acc[2][5];
#pragma unroll
    for (int j = 0; j < 5; j++) { acc[0][j] = 0ull; acc[1][j] = 0ull; }
    u64 s2[2] = {0ull, 0ull};

#pragma unroll
    for (int P = 0; P < 2; P++) {
        // ---- Stage 64 c x 256 px into SMEM (coalesced float4, 8 per thread)
        __syncthreads();    // protect s_x reuse (and proto-norm writes on P=0)
        const float* src = fbh + (size_t)(P * 64) * HW;
        float4* dst4 = (float4*)s_x;
#pragma unroll
        for (int i = 0; i < 8; i++) {
            int idx = tid + i * 512;            // 0..4095 ; c = idx>>6, q = idx&63
            int c = idx >> 6, q = idx & 63;
            dst4[idx] = *(const float4*)(src + (size_t)c * HW + q * 4);
        }
        __syncthreads();

        // ---- Norms for these 64 c, from SMEM. Warp w: c_local = 4w..4w+3.
#pragma unroll
        for (int j = 0; j < 4; j++) {
            int cl = w * 4 + j;
            float4 a = *(const float4*)(s_x + cl * 256 + lane * 8);
            float4 bq = *(const float4*)(s_x + cl * 256 + lane * 8 + 4);
            float s = wred(dot4(a) + dot4(bq));
            if (lane == 0) {
                float r = 1.0f / fmaxf(sqrtf(s), EPSV);
                s_inv[cl] = r;
                s_r2[cl] = pk2(r * r, r * r);
            }
        }
        __syncthreads();

        // ---- Fold protos for this phase: s_pn[(cl*4+kg)*6+j] = p[k][P*64+cl]*pinv_k*inv_cl
        for (int i = tid; i < 64 * KK; i += 512) {
            int cl = i / KK, k = i - cl * KK;
            int kg_ = k / 5, jj = k - kg_ * 5;
            float val = __ldg(p + k * CC + P * 64 + cl) * s_pinv[k] * s_inv[cl];
            s_pn[(cl * 4 + kg_) * 6 + jj] = pk2(val, val);
        }
        __syncthreads();

        // ---- Dot loop over this phase's 32 c (per ch half), all-SMEM
        int cl0 = ch * 32;
        const u64* pb = s_pn + kg * 6;
#pragma unroll
        for (int seg = 0; seg < 4; seg++) {
            if (seg == kg) seg8<true >(s_x, cl0 + seg * 8, pxg, pb, s_r2, acc, s2);
            else           seg8<false>(s_x, cl0 + seg * 8, pxg, pb, s_r2, acc, s2);
        }
    }

    // ---- s2 reduction over the 8 (ch,kg) groups
    int grp = ch * 4 + kg;
    s_s2p[(size_t)grp * 128 + 2 * pxg]     = s2[0];
    s_s2p[(size_t)grp * 128 + 2 * pxg + 1] = s2[1];
    __syncthreads();
    if (tid < 128) {
        u64 t = 0ull;
#pragma unroll
        for (int g = 0; g < 8; g++) t = add2_(t, s_s2p[g * 128 + tid]);
        s_s2[tid] = t;
    }

    // ---- Cross-ch dot reduction + epilogue (s_red aliases dead s_x)
    u64* s_red = (u64*)s_x;            // [256 threads][10]
    if (ch == 1) {
        u64* r = s_red + (size_t)(tid & 255) * 10;
#pragma unroll
        for (int i = 0; i < 2; i++)
#pragma unroll
            for (int j = 0; j < 5; j++) r[i * 5 + j] = acc[i][j];
    }
    __syncthreads();

    if (ch == 0) {
        const u64* r = s_red + (size_t)tid * 10;
#pragma unroll
        for (int i = 0; i < 2; i++)
#pragma unroll
            for (int j = 0; j < 5; j++) acc[i][j] = add2_(acc[i][j], r[i * 5 + j]);

        float n0, n1, n2, n3;
        upk2(s_s2[2 * pxg], n0, n1);
        upk2(s_s2[2 * pxg + 1], n2, n3);

        float scale = fabsf(ds[0]);
        float* ob = out + (size_t)b * KK * HW + (size_t)h * WW + 4 * pxg;
#pragma unroll
        for (int j = 0; j < 5; j++) {
            int k = kg * 5 + j;
            float q = s_pn2[k];
            float d0, d1, d2, d3;
            upk2(acc[0][j], d0, d1);
            upk2(acc[1][j], d2, d3);
            float4 o;
            o.x = -scale * sqrtf(fmaxf(n0 + q - 2.0f * d0, 0.0f));
            o.y = -scale * sqrtf(fmaxf(n1 + q - 2.0f * d1, 0.0f));
            o.z = -scale * sqrtf(fmaxf(n2 + q - 2.0f * d2, 0.0f));
            o.w = -scale * sqrtf(fmaxf(n3 + q - 2.0f * d3, 0.0f));
            *(float4*)(ob + (size_t)k * HW) = o;
        }
    }
}

extern "C" void kernel_launch(void* const* d_in, const int* in_sizes, int n_in,
                              void* d_out, int out_size) {
    const float* features   = (const float*)d_in[0];
    const float* prototypes = (const float*)d_in[1];
    const float* dscale     = (const float*)d_in[2];
    float* out = (float*)d_out;

    cudaFuncSetAttribute(iso_kernel, cudaFuncAttributeMaxDynamicSharedMemorySize, 65536);
    iso_kernel<<<BB * HH, 512, 65536>>>(features, prototypes, dscale, out);
}